// round 3
// baseline (speedup 1.0000x reference)
#include <cuda_runtime.h>
#include <math.h>

#define N_NODES 12288
#define N_EDGES 196608
#define F_IN    1433
#define H1      32
#define H2      16
#define NCLS    7
#define KSPLIT  8
#define KCHUNK  180   // ceil(1433/8); last chunk = 173

// ---- scratch (static device globals; no allocation allowed) ----
__device__ float g_xw  [N_NODES * H1];   // x @ W1
__device__ float g_h   [N_NODES * H1];   // relu(A_norm @ xw + b1)
__device__ float g_agg1[N_NODES * H1];   // GCN neighbor accumulation (edges only)
__device__ float g_agg2[N_NODES * H1];   // SAGE sum over h[dst] grouped by src
__device__ float g_deg [N_NODES];
__device__ float g_cnt [N_NODES];
__device__ float g_dis [N_NODES];
__device__ int   g_row [N_EDGES];        // decoded edge_index[0]
__device__ int   g_col [N_EDGES];        // decoded edge_index[1]
__device__ int   g_is64;                 // 1 if edge buffer is int64, 0 if int32

// ---- K0: probe index dtype. int64 little-endian high words (odd int32 slots)
// are all zero (indices in [0, 12288)); int32 data at odd slots is random
// node ids, so any nonzero => int32. ----
__global__ void k_probe(const int* __restrict__ ei32) {
    __shared__ int s;
    if (threadIdx.x == 0) s = 0;
    __syncthreads();
    // check odd words among the first 2048 ints (in-bounds for both layouts)
    int v = ei32[2 * threadIdx.x + 1] | ei32[2 * threadIdx.x + 1025];
    if (v != 0) atomicOr(&s, 1);
    __syncthreads();
    if (threadIdx.x == 0) g_is64 = (s == 0) ? 1 : 0;
}

// ---- K1: init scratch ----
__global__ void k_init() {
    int i = blockIdx.x * blockDim.x + threadIdx.x;
    if (i < N_NODES * H1) {
        g_xw[i] = 0.f; g_agg1[i] = 0.f; g_agg2[i] = 0.f;
    }
    if (i < N_NODES) {
        g_deg[i] = 1.f;   // self loop contributes 1 to deg (col includes loops)
        g_cnt[i] = 0.f;
    }
}

// ---- K2: decode indices (dtype-agnostic) + degree/count atomics ----
__global__ void k_decode(const int* __restrict__ ei32) {
    int e = blockIdx.x * blockDim.x + threadIdx.x;
    if (e >= N_EDGES) return;
    int r, c;
    if (g_is64) {
        r = ei32[2 * e];                 // low word of int64 edge_index[0][e]
        c = ei32[2 * (N_EDGES + e)];     // low word of int64 edge_index[1][e]
    } else {
        r = ei32[e];
        c = ei32[N_EDGES + e];
    }
    g_row[e] = r;
    g_col[e] = c;
    atomicAdd(&g_deg[c], 1.f);
    atomicAdd(&g_cnt[r], 1.f);
}

// ---- K3: xw = x @ W1  (M=12288, K=1433, N=32), K split 8 ways, atomic accumulate ----
__global__ void __launch_bounds__(256) k_gemm1(const float* __restrict__ x,
                                               const float* __restrict__ W1) {
    __shared__ float sw[KCHUNK * H1];   // 23040 B
    const int s    = blockIdx.y;
    const int k0   = s * KCHUNK;
    const int klen = min(KCHUNK, F_IN - k0);

    for (int i = threadIdx.x; i < klen * H1; i += blockDim.x)
        sw[i] = W1[k0 * H1 + i];
    __syncthreads();

    const int row = blockIdx.x * blockDim.x + threadIdx.x;   // grid sized exactly
    float acc[H1];
#pragma unroll
    for (int c = 0; c < H1; c++) acc[c] = 0.f;

    const float* __restrict__ xr = x + (size_t)row * F_IN + k0;
#pragma unroll 4
    for (int k = 0; k < klen; k++) {
        const float a = __ldg(xr + k);
        const float4* __restrict__ w4 = (const float4*)(sw + k * H1);
#pragma unroll
        for (int c4 = 0; c4 < 8; c4++) {
            float4 w = w4[c4];   // warp-broadcast LDS.128 (all lanes same k)
            acc[c4 * 4 + 0] = fmaf(a, w.x, acc[c4 * 4 + 0]);
            acc[c4 * 4 + 1] = fmaf(a, w.y, acc[c4 * 4 + 1]);
            acc[c4 * 4 + 2] = fmaf(a, w.z, acc[c4 * 4 + 2]);
            acc[c4 * 4 + 3] = fmaf(a, w.w, acc[c4 * 4 + 3]);
        }
    }

    float* o = g_xw + row * H1;
#pragma unroll
    for (int c = 0; c < H1; c++) atomicAdd(o + c, acc[c]);
}

// ---- K4: dis = deg^-1/2 ----
__global__ void k_dis() {
    int i = blockIdx.x * blockDim.x + threadIdx.x;
    if (i < N_NODES) {
        float d = g_deg[i];
        g_dis[i] = (d > 0.f) ? rsqrtf(d) : 0.f;
    }
}

// ---- K5: GCN scatter: agg1[row] += dis[row]*dis[col]*xw[col], one warp per edge ----
__global__ void k_scatter1() {
    int t = blockIdx.x * blockDim.x + threadIdx.x;
    int e = t >> 5;
    if (e >= N_EDGES) return;
    int lane = t & 31;
    int r = g_row[e];
    int c = g_col[e];
    float w = g_dis[r] * g_dis[c];
    atomicAdd(&g_agg1[r * H1 + lane], w * g_xw[c * H1 + lane]);
}

// ---- K6: h = relu(agg1 + selfloop + b1) ----
__global__ void k_hidden(const float* __restrict__ b1) {
    int i = blockIdx.x * blockDim.x + threadIdx.x;
    if (i >= N_NODES * H1) return;
    int node = i >> 5;
    int c    = i & 31;
    float d = g_dis[node];
    float v = g_agg1[i] + d * d * g_xw[i] + __ldg(b1 + c);
    g_h[i] = fmaxf(v, 0.f);
}

// ---- K7: SAGE scatter: agg2[src] += h[dst], one warp per edge ----
__global__ void k_scatter2() {
    int t = blockIdx.x * blockDim.x + threadIdx.x;
    int e = t >> 5;
    if (e >= N_EDGES) return;
    int lane = t & 31;
    int r = g_row[e];   // src
    int c = g_col[e];   // dst
    atomicAdd(&g_agg2[r * H1 + lane], g_h[c * H1 + lane]);
}

// ---- K8: head: mean-agg, relu(h@Wl + agg@Wr + biases), L2 norm, W3, softmax ----
__global__ void __launch_bounds__(256) k_head(const float* __restrict__ Wl,
                                              const float* __restrict__ bl,
                                              const float* __restrict__ Wr,
                                              const float* __restrict__ br,
                                              const float* __restrict__ W3,
                                              const float* __restrict__ b3,
                                              float* __restrict__ out) {
    const unsigned FULL = 0xffffffffu;
    int gw   = (blockIdx.x * blockDim.x + threadIdx.x) >> 5;  // node = global warp id
    int lane = threadIdx.x & 31;
    if (gw >= N_NODES) return;

    float hv = g_h[gw * H1 + lane];
    float av = g_agg2[gw * H1 + lane];
    float cv = g_cnt[gw];
    av = (cv > 0.f) ? av / cv : 0.f;   // mean over neighbors; 0 if no out-edges

    float o = 0.f;
    if (lane < H2) o = __ldg(bl + lane) + __ldg(br + lane);
#pragma unroll
    for (int k = 0; k < H1; k++) {
        float hk = __shfl_sync(FULL, hv, k);
        float ak = __shfl_sync(FULL, av, k);
        if (lane < H2)
            o = fmaf(hk, __ldg(Wl + k * H2 + lane),
                fmaf(ak, __ldg(Wr + k * H2 + lane), o));
    }
    o = fmaxf(o, 0.f);   // lanes >= 16 hold 0

    // L2 norm over the 16 valid lanes (xor 1/2/4/8 stays within the 16-group)
    float ss = o * o;
#pragma unroll
    for (int off = 8; off > 0; off >>= 1) ss += __shfl_xor_sync(FULL, ss, off);
    float inv = 1.f / (sqrtf(ss) + 1e-6f);
    float on  = o * inv;

    // logits = on @ W3 + b3
    float l = (lane < NCLS) ? __ldg(b3 + lane) : -1e30f;
#pragma unroll
    for (int c = 0; c < H2; c++) {
        float oc = __shfl_sync(FULL, on, c);
        if (lane < NCLS) l = fmaf(oc, __ldg(W3 + c * NCLS + lane), l);
    }

    // softmax across lanes 0..6 (8-lane xor group; lane 7 = -1e30 -> exp = 0)
    float m = l;
#pragma unroll
    for (int off = 4; off > 0; off >>= 1) m = fmaxf(m, __shfl_xor_sync(FULL, m, off));
    float ev = expf(l - m);
    float sm = ev;
#pragma unroll
    for (int off = 4; off > 0; off >>= 1) sm += __shfl_xor_sync(FULL, sm, off);

    if (lane < NCLS) out[gw * NCLS + lane] = ev / sm;
}

extern "C" void kernel_launch(void* const* d_in, const int* in_sizes, int n_in,
                              void* d_out, int out_size) {
    const float* x  = (const float*)d_in[0];
    const int*   ei = (const int*)d_in[1];     // int32 view; dtype probed on device
    const float* W1 = (const float*)d_in[2];
    const float* b1 = (const float*)d_in[3];
    const float* Wl = (const float*)d_in[4];
    const float* bl = (const float*)d_in[5];
    const float* Wr = (const float*)d_in[6];
    const float* br = (const float*)d_in[7];
    const float* W3 = (const float*)d_in[8];
    const float* b3 = (const float*)d_in[9];
    float* out = (float*)d_out;

    const int T = 256;
    k_probe<<<1, 512>>>(ei);
    k_init<<<(N_NODES * H1 + T - 1) / T, T>>>();
    k_decode<<<(N_EDGES + T - 1) / T, T>>>(ei);
    {
        dim3 grid(N_NODES / T, KSPLIT);   // 48 x 8
        k_gemm1<<<grid, T>>>(x, W1);
    }
    k_dis<<<(N_NODES + T - 1) / T, T>>>();
    k_scatter1<<<(N_EDGES * 32 + T - 1) / T, T>>>();
    k_hidden<<<(N_NODES * H1 + T - 1) / T, T>>>(b1);
    k_scatter2<<<(N_EDGES * 32 + T - 1) / T, T>>>();
    k_head<<<(N_NODES + 7) / 8, T>>>(Wl, bl, Wr, br, W3, b3, out);
}